// round 1
// baseline (speedup 1.0000x reference)
#include <cuda_runtime.h>
#include <cstdint>

#define GQ     640
#define NIMG   320
#define NCOIL  12
#define MPTS   102400
#define PI_F   3.14159265358979f
#define BETA_F 13.855101f      // pi * sqrt((6*1.5/2)^2 - 0.8)
#define INV_G  0.0015625f      // 1/640

// Scratch (zero-initialized at module load; middle rows of g_gridA are never
// written by anyone, so they remain zero across graph replays).
__device__ float2 g_gridA[NCOIL * GQ * GQ];
__device__ float2 g_gridB[NCOIL * GQ * GQ];
__device__ float  g_scale[NIMG];

__constant__ float c5r[5] = {1.0f, 0.30901699f, -0.80901699f, -0.80901699f, 0.30901699f};
__constant__ float c5i[5] = {0.0f, -0.95105652f, -0.58778525f, 0.58778525f, 0.95105652f};

// ---------------------------------------------------------------------------
// Modified Bessel I0 (Abramowitz & Stegun 9.8.1 / 9.8.2, ~2e-7 rel error)
// ---------------------------------------------------------------------------
__device__ __forceinline__ float i0f_dev(float x) {
    if (x < 3.75f) {
        float t = x * (1.0f / 3.75f);
        t *= t;
        return 1.0f + t * (3.5156229f + t * (3.0899424f + t * (1.2067492f
             + t * (0.2659732f + t * (0.0360768f + t * 0.0045813f)))));
    } else {
        float t = 3.75f / x;
        float p = 0.39894228f + t * (0.01328592f + t * (0.00225319f + t * (-0.00157565f
                + t * (0.00916281f + t * (-0.02057706f + t * (0.02635537f
                + t * (-0.01647633f + t * 0.00392377f)))))));
        return expf(x) * rsqrtf(x) * p;
    }
}

// Kaiser-Bessel kernel, support |u| <= 3 (J=6)
__device__ __forceinline__ float kbf(float u) {
    float m = fabsf(u) * (1.0f / 3.0f);
    float a = 1.0f - m * m;
    a = a > 0.0f ? a : 0.0f;
    float v = i0f_dev(BETA_F * sqrtf(a)) * (1.0f / 6.0f);
    return (m <= 1.0f) ? v : 0.0f;
}

// ---------------------------------------------------------------------------
// Apodization scale (length 320, same for both dims: N=320, G=640)
// ---------------------------------------------------------------------------
__global__ void apod_kernel() {
    int n = threadIdx.x;
    if (n < NIMG) {
        float acc = 0.0f;
        #pragma unroll
        for (int j = -6; j <= 6; j++) {
            float kv = kbf((float)j);
            acc += kv * cosf(2.0f * PI_F * (float)j * ((float)n - 160.0f) * (1.0f / 640.0f));
        }
        g_scale[n] = 1.0f / acc;
    }
}

// ---------------------------------------------------------------------------
// 640-point forward FFT in shared memory. 640 = 5 * 128.
// Input layout in A:  A[n1*128 + n2] = x[5*n2 + n1]
// Output (natural order X[k]) ends in A. Requires blockDim.x == 320.
// ---------------------------------------------------------------------------
__device__ void fft640(float2* A, float2* B, int t) {
    float2* src = A;
    float2* dst = B;
    int n = 128;
    const int n1 = t >> 6;   // which of the 5 sub-FFTs
    const int b  = t & 63;   // butterfly index within sub-FFT
    #pragma unroll
    for (int stage = 0; stage < 7; stage++) {
        int s = 1 << stage;
        int m = n >> 1;
        int q = b & (s - 1);
        int p = b >> stage;
        float2 a  = src[(n1 << 7) + q + s * p];
        float2 bb = src[(n1 << 7) + q + s * (p + m)];
        float ang = -(2.0f * PI_F) * (float)p / (float)n;
        float sn, cs;
        __sincosf(ang, &sn, &cs);
        float2 e = make_float2(a.x + bb.x, a.y + bb.y);
        float dx = a.x - bb.x, dy = a.y - bb.y;
        float2 o = make_float2(dx * cs - dy * sn, dx * sn + dy * cs);
        dst[(n1 << 7) + q + s * 2 * p]       = e;
        dst[(n1 << 7) + q + s * (2 * p + 1)] = o;
        __syncthreads();
        float2* tmp = src; src = dst; dst = tmp;
        n = m;
    }
    // After 7 stages: F[n1][k2] sits in src (== B). Twiddle + radix-5 -> dst (== A).
    if (t < 128) {
        int k2 = t;
        float2 g[5];
        #pragma unroll
        for (int j = 0; j < 5; j++) {
            float2 f = src[(j << 7) + k2];
            int idx = (j * k2) % 640;
            if (idx >= 320) idx -= 640;              // keep |ang| <= pi for __sincosf
            float ang = -(2.0f * PI_F / 640.0f) * (float)idx;
            float sn, cs;
            __sincosf(ang, &sn, &cs);
            g[j] = make_float2(f.x * cs - f.y * sn, f.x * sn + f.y * cs);
        }
        #pragma unroll
        for (int k1 = 0; k1 < 5; k1++) {
            float rx = 0.0f, ry = 0.0f;
            #pragma unroll
            for (int j = 0; j < 5; j++) {
                int id = (j * k1) % 5;
                float cr = c5r[id], ci = c5i[id];
                rx += g[j].x * cr - g[j].y * ci;
                ry += g[j].x * ci + g[j].y * cr;
            }
            dst[(k1 << 7) + k2] = make_float2(rx, ry);
        }
    }
    __syncthreads();
}

// ---------------------------------------------------------------------------
// Row pass: fused coil-multiply + apodization + pad + ifftshift + row FFT.
// Only 320 of 640 shifted rows are nonzero: r in [0,160) U [480,640).
// grid = (320 rows, 12 coils), block = 320.
// ---------------------------------------------------------------------------
__global__ void row_fft_kernel(const float* __restrict__ img_r, const float* __restrict__ img_i,
                               const float* __restrict__ sm_r,  const float* __restrict__ sm_i) {
    __shared__ float2 A[GQ];
    __shared__ float2 B[GQ];
    int coil = blockIdx.y;
    int rr   = blockIdx.x;                         // 0..319
    int r = (rr < 160) ? rr : rr + 320;            // shifted grid row
    int i = (rr < 160) ? rr + 160 : rr - 160;      // source image row
    int t = threadIdx.x;
    float si = g_scale[i];

    #pragma unroll
    for (int kk = 0; kk < 2; kk++) {
        int cc = t + kk * 320;                     // shifted grid column
        float2 v = make_float2(0.0f, 0.0f);
        if (cc < 160 || cc >= 480) {
            int j = (cc < 160) ? cc + 160 : cc - 480;
            float ir  = img_r[i * NIMG + j];
            float ii  = img_i[i * NIMG + j];
            float sr  = sm_r[((size_t)coil * NIMG + i) * NIMG + j];
            float sim = sm_i[((size_t)coil * NIMG + i) * NIMG + j];
            float sc  = si * g_scale[j];
            v.x = (ir * sr - ii * sim) * sc;
            v.y = (ir * sim + ii * sr) * sc;
        }
        A[(cc % 5) * 128 + cc / 5] = v;
    }
    __syncthreads();
    fft640(A, B, t);
    float2* gout = g_gridA + ((size_t)coil * GQ + r) * GQ;
    for (int k = t; k < GQ; k += 320) gout[k] = A[k];
}

// ---------------------------------------------------------------------------
// Column pass: 4 columns per block staged through SMEM for coalescing.
// grid = (160 col-groups, 12 coils), block = 320. Writes gridB (x 1/640).
// ---------------------------------------------------------------------------
#define COLS_PER_BLK 4
#define SPITCH 642
__global__ void col_fft_kernel() {
    __shared__ float2 S[COLS_PER_BLK * SPITCH];
    __shared__ float2 A[GQ];
    __shared__ float2 B[GQ];
    int coil = blockIdx.y;
    int c0 = blockIdx.x * COLS_PER_BLK;
    const float2* gin = g_gridA + (size_t)coil * GQ * GQ;

    for (int idx = threadIdx.x; idx < GQ * COLS_PER_BLK; idx += 320) {
        int row = idx >> 2, col = idx & 3;
        S[col * SPITCH + row] = gin[(size_t)row * GQ + c0 + col];
    }
    __syncthreads();

    for (int col = 0; col < COLS_PER_BLK; col++) {
        for (int k = threadIdx.x; k < GQ; k += 320)
            A[(k % 5) * 128 + k / 5] = S[col * SPITCH + k];
        __syncthreads();
        fft640(A, B, threadIdx.x);
        for (int k = threadIdx.x; k < GQ; k += 320) {
            float2 v = A[k];
            S[col * SPITCH + k] = make_float2(v.x * INV_G, v.y * INV_G);
        }
        __syncthreads();
    }

    float2* gout = g_gridB + (size_t)coil * GQ * GQ;
    for (int idx = threadIdx.x; idx < GQ * COLS_PER_BLK; idx += 320) {
        int row = idx >> 2, col = idx & 3;
        gout[(size_t)row * GQ + c0 + col] = S[col * SPITCH + row];
    }
}

// ---------------------------------------------------------------------------
// KB interpolation taps (matches reference interp_weights)
// ---------------------------------------------------------------------------
__device__ __forceinline__ void taps(float om, int* idx, float* w) {
    float t = fmodf((om * 640.0f) / 6.2831855f, 640.0f);
    if (t < 0.0f) t += 640.0f;
    float base = floorf(t);
    #pragma unroll
    for (int j = 0; j < 6; j++) {
        float k = base + (float)(j - 2);
        w[j] = kbf(t - k);
        int ki = (int)k;                    // in [-2, 643]
        if (ki < 0) ki += 640;
        else if (ki >= 640) ki -= 640;
        idx[j] = ki;
    }
}

// ---------------------------------------------------------------------------
// Interpolation: thread per sample, loop over 12 coils, 6x6 KB gather.
// ---------------------------------------------------------------------------
__global__ void interp_kernel(const float* __restrict__ ktraj, float* __restrict__ out) {
    int m = blockIdx.x * blockDim.x + threadIdx.x;
    if (m >= MPTS) return;

    int ix[6], iy[6];
    float wx[6], wy[6];
    taps(ktraj[m],        ix, wx);   // om[0] -> rows (axis G1)
    taps(ktraj[MPTS + m], iy, wy);   // om[1] -> cols (axis G2)

    int rowoff[6];
    #pragma unroll
    for (int i = 0; i < 6; i++) rowoff[i] = ix[i] * GQ;

    #pragma unroll 1
    for (int c = 0; c < NCOIL; c++) {
        const float2* gb = g_gridB + (size_t)c * (GQ * GQ);
        float sx = 0.0f, sy = 0.0f;
        #pragma unroll
        for (int i = 0; i < 6; i++) {
            const float2* p = gb + rowoff[i];
            float rx = 0.0f, ry = 0.0f;
            #pragma unroll
            for (int j = 0; j < 6; j++) {
                float2 v = __ldg(p + iy[j]);
                rx += v.x * wy[j];
                ry += v.y * wy[j];
            }
            sx += wx[i] * rx;
            sy += wx[i] * ry;
        }
        size_t o = ((size_t)c * MPTS + m) * 2;
        out[o]     = sx;
        out[o + 1] = sy;
    }
}

// ---------------------------------------------------------------------------
extern "C" void kernel_launch(void* const* d_in, const int* in_sizes, int n_in,
                              void* d_out, int out_size) {
    const float* img_r = (const float*)d_in[0];
    const float* img_i = (const float*)d_in[1];
    const float* sm_r  = (const float*)d_in[2];
    const float* sm_i  = (const float*)d_in[3];
    const float* kt    = (const float*)d_in[4];
    float* out = (float*)d_out;

    apod_kernel<<<1, 320>>>();
    row_fft_kernel<<<dim3(320, NCOIL), 320>>>(img_r, img_i, sm_r, sm_i);
    col_fft_kernel<<<dim3(GQ / COLS_PER_BLK, NCOIL), 320>>>();
    interp_kernel<<<(MPTS + 255) / 256, 256>>>(kt, out);
}

// round 2
// speedup vs baseline: 1.0606x; 1.0606x over previous
#include <cuda_runtime.h>
#include <cstdint>

#define GQ     640
#define NIMG   320
#define NCOIL  12
#define MPTS   102400
#define PI_F   3.14159265358979f
#define BETA_F 13.855101f      // pi * sqrt((6*1.5/2)^2 - 0.8)
#define INV_G  0.0015625f      // 1/640

// Scratch (zero-initialized at module load; middle rows of g_gridA are never
// written by anyone, so they remain zero across graph replays).
__device__ float2 g_gridA[NCOIL * GQ * GQ];
__device__ float2 g_gridB[NCOIL * GQ * GQ];
__device__ float  g_scale[NIMG];

__constant__ float c5r[5] = {1.0f, 0.30901699f, -0.80901699f, -0.80901699f, 0.30901699f};
__constant__ float c5i[5] = {0.0f, -0.95105652f, -0.58778525f, 0.58778525f, 0.95105652f};

// ---------------------------------------------------------------------------
// Modified Bessel I0 (Abramowitz & Stegun 9.8.1 / 9.8.2, ~2e-7 rel error)
// ---------------------------------------------------------------------------
__device__ __forceinline__ float i0f_dev(float x) {
    if (x < 3.75f) {
        float t = x * (1.0f / 3.75f);
        t *= t;
        return 1.0f + t * (3.5156229f + t * (3.0899424f + t * (1.2067492f
             + t * (0.2659732f + t * (0.0360768f + t * 0.0045813f)))));
    } else {
        float t = 3.75f / x;
        float p = 0.39894228f + t * (0.01328592f + t * (0.00225319f + t * (-0.00157565f
                + t * (0.00916281f + t * (-0.02057706f + t * (0.02635537f
                + t * (-0.01647633f + t * 0.00392377f)))))));
        return expf(x) * rsqrtf(x) * p;
    }
}

// Kaiser-Bessel kernel, support |u| <= 3 (J=6)
__device__ __forceinline__ float kbf(float u) {
    float m = fabsf(u) * (1.0f / 3.0f);
    float a = 1.0f - m * m;
    a = a > 0.0f ? a : 0.0f;
    float v = i0f_dev(BETA_F * sqrtf(a)) * (1.0f / 6.0f);
    return (m <= 1.0f) ? v : 0.0f;
}

// ---------------------------------------------------------------------------
// Apodization scale (length 320, same for both dims: N=320, G=640)
// ---------------------------------------------------------------------------
__global__ void apod_kernel() {
    int n = threadIdx.x;
    if (n < NIMG) {
        float acc = 0.0f;
        #pragma unroll
        for (int j = -6; j <= 6; j++) {
            float kv = kbf((float)j);
            acc += kv * cosf(2.0f * PI_F * (float)j * ((float)n - 160.0f) * (1.0f / 640.0f));
        }
        g_scale[n] = 1.0f / acc;
    }
}

// ---------------------------------------------------------------------------
// 640-point forward FFT in shared memory. 640 = 5 * 128.
// Input layout in A:  A[n1*128 + n2] = x[5*n2 + n1]
// Output (natural order X[k]) ends in A. Requires blockDim.x == 320.
// ---------------------------------------------------------------------------
__device__ void fft640(float2* A, float2* B, int t) {
    float2* src = A;
    float2* dst = B;
    int n = 128;
    const int n1 = t >> 6;   // which of the 5 sub-FFTs
    const int b  = t & 63;   // butterfly index within sub-FFT
    #pragma unroll
    for (int stage = 0; stage < 7; stage++) {
        int s = 1 << stage;
        int m = n >> 1;
        int q = b & (s - 1);
        int p = b >> stage;
        float2 a  = src[(n1 << 7) + q + s * p];
        float2 bb = src[(n1 << 7) + q + s * (p + m)];
        float ang = -(2.0f * PI_F) * (float)p / (float)n;
        float sn, cs;
        __sincosf(ang, &sn, &cs);
        float2 e = make_float2(a.x + bb.x, a.y + bb.y);
        float dx = a.x - bb.x, dy = a.y - bb.y;
        float2 o = make_float2(dx * cs - dy * sn, dx * sn + dy * cs);
        dst[(n1 << 7) + q + s * 2 * p]       = e;
        dst[(n1 << 7) + q + s * (2 * p + 1)] = o;
        __syncthreads();
        float2* tmp = src; src = dst; dst = tmp;
        n = m;
    }
    // After 7 stages: F[n1][k2] sits in src (== B). Twiddle + radix-5 -> dst (== A).
    if (t < 128) {
        int k2 = t;
        float2 g[5];
        #pragma unroll
        for (int j = 0; j < 5; j++) {
            float2 f = src[(j << 7) + k2];
            int idx = (j * k2) % 640;
            if (idx >= 320) idx -= 640;              // keep |ang| <= pi for __sincosf
            float ang = -(2.0f * PI_F / 640.0f) * (float)idx;
            float sn, cs;
            __sincosf(ang, &sn, &cs);
            g[j] = make_float2(f.x * cs - f.y * sn, f.x * sn + f.y * cs);
        }
        #pragma unroll
        for (int k1 = 0; k1 < 5; k1++) {
            float rx = 0.0f, ry = 0.0f;
            #pragma unroll
            for (int j = 0; j < 5; j++) {
                int id = (j * k1) % 5;
                float cr = c5r[id], ci = c5i[id];
                rx += g[j].x * cr - g[j].y * ci;
                ry += g[j].x * ci + g[j].y * cr;
            }
            dst[(k1 << 7) + k2] = make_float2(rx, ry);
        }
    }
    __syncthreads();
}

// ---------------------------------------------------------------------------
// Row pass: fused coil-multiply + apodization + pad + ifftshift + row FFT.
// Only 320 of 640 shifted rows are nonzero: r in [0,160) U [480,640).
// grid = (320 rows, 12 coils), block = 320.
// ---------------------------------------------------------------------------
__global__ void row_fft_kernel(const float* __restrict__ img_r, const float* __restrict__ img_i,
                               const float* __restrict__ sm_r,  const float* __restrict__ sm_i) {
    __shared__ float2 A[GQ];
    __shared__ float2 B[GQ];
    int coil = blockIdx.y;
    int rr   = blockIdx.x;                         // 0..319
    int r = (rr < 160) ? rr : rr + 320;            // shifted grid row
    int i = (rr < 160) ? rr + 160 : rr - 160;      // source image row
    int t = threadIdx.x;
    float si = g_scale[i];

    #pragma unroll
    for (int kk = 0; kk < 2; kk++) {
        int cc = t + kk * 320;                     // shifted grid column
        float2 v = make_float2(0.0f, 0.0f);
        if (cc < 160 || cc >= 480) {
            int j = (cc < 160) ? cc + 160 : cc - 480;
            float ir  = img_r[i * NIMG + j];
            float ii  = img_i[i * NIMG + j];
            float sr  = sm_r[((size_t)coil * NIMG + i) * NIMG + j];
            float sim = sm_i[((size_t)coil * NIMG + i) * NIMG + j];
            float sc  = si * g_scale[j];
            v.x = (ir * sr - ii * sim) * sc;
            v.y = (ir * sim + ii * sr) * sc;
        }
        A[(cc % 5) * 128 + cc / 5] = v;
    }
    __syncthreads();
    fft640(A, B, t);
    float2* gout = g_gridA + ((size_t)coil * GQ + r) * GQ;
    for (int k = t; k < GQ; k += 320) gout[k] = A[k];
}

// ---------------------------------------------------------------------------
// Column pass: 4 columns per block staged through SMEM for coalescing.
// grid = (160 col-groups, 12 coils), block = 320. Writes gridB (x 1/640).
// ---------------------------------------------------------------------------
#define COLS_PER_BLK 4
#define SPITCH 642
__global__ void col_fft_kernel() {
    __shared__ float2 S[COLS_PER_BLK * SPITCH];
    __shared__ float2 A[GQ];
    __shared__ float2 B[GQ];
    int coil = blockIdx.y;
    int c0 = blockIdx.x * COLS_PER_BLK;
    const float2* gin = g_gridA + (size_t)coil * GQ * GQ;

    for (int idx = threadIdx.x; idx < GQ * COLS_PER_BLK; idx += 320) {
        int row = idx >> 2, col = idx & 3;
        S[col * SPITCH + row] = gin[(size_t)row * GQ + c0 + col];
    }
    __syncthreads();

    for (int col = 0; col < COLS_PER_BLK; col++) {
        for (int k = threadIdx.x; k < GQ; k += 320)
            A[(k % 5) * 128 + k / 5] = S[col * SPITCH + k];
        __syncthreads();
        fft640(A, B, threadIdx.x);
        for (int k = threadIdx.x; k < GQ; k += 320) {
            float2 v = A[k];
            S[col * SPITCH + k] = make_float2(v.x * INV_G, v.y * INV_G);
        }
        __syncthreads();
    }

    float2* gout = g_gridB + (size_t)coil * GQ * GQ;
    for (int idx = threadIdx.x; idx < GQ * COLS_PER_BLK; idx += 320) {
        int row = idx >> 2, col = idx & 3;
        gout[(size_t)row * GQ + c0 + col] = S[col * SPITCH + row];
    }
}

// ---------------------------------------------------------------------------
// Interpolation v2: block = 384 threads = 32 samples x 12 coils.
// Phase 1: each thread computes exactly ONE KB tap (weight + index) -> smem.
// Phase 2: thread (coil, s) does the 6x6 gather for one (sample, coil) pair.
// Low register count -> high occupancy to hide the scattered-gather latency.
// ---------------------------------------------------------------------------
#define SAMP_PER_BLK 32
__global__ void __launch_bounds__(384) interp_kernel(const float* __restrict__ ktraj,
                                                     float* __restrict__ out) {
    __shared__ float s_w[2][SAMP_PER_BLK][6];   // [dim][sample][tap]
    __shared__ int   s_i[2][SAMP_PER_BLK][6];   // dim0: precomputed row*GQ, dim1: col
    const int m0 = blockIdx.x * SAMP_PER_BLK;
    const int t  = threadIdx.x;

    // --- phase 1: 384 threads == 32 samples * 12 taps ---
    {
        int s   = t / 12;
        int r   = t - s * 12;
        int dim = r >= 6 ? 1 : 0;
        int j   = r - dim * 6;
        float om = ktraj[dim * MPTS + (m0 + s)];
        float tt = fmodf((om * 640.0f) / 6.2831855f, 640.0f);
        if (tt < 0.0f) tt += 640.0f;
        float base = floorf(tt);
        float k = base + (float)(j - 2);
        float w = kbf(tt - k);
        int ki = (int)k;                    // in [-2, 643]
        if (ki < 0) ki += 640;
        else if (ki >= 640) ki -= 640;
        s_w[dim][s][j] = w;
        s_i[dim][s][j] = (dim == 0) ? ki * GQ : ki;
    }
    __syncthreads();

    // --- phase 2: coil = t/32 (warp-uniform), s = lane ---
    const int coil = t >> 5;
    const int s    = t & 31;
    const int m    = m0 + s;

    float wx[6], wy[6];
    int rowoff[6], iy[6];
    #pragma unroll
    for (int i = 0; i < 6; i++) {
        wx[i]     = s_w[0][s][i];
        wy[i]     = s_w[1][s][i];
        rowoff[i] = s_i[0][s][i];
        iy[i]     = s_i[1][s][i];
    }

    const float2* __restrict__ gb = g_gridB + (size_t)coil * (GQ * GQ);
    float sx = 0.0f, sy = 0.0f;
    #pragma unroll
    for (int i = 0; i < 6; i++) {
        const float2* p = gb + rowoff[i];
        float rx = 0.0f, ry = 0.0f;
        #pragma unroll
        for (int j = 0; j < 6; j++) {
            float2 v = __ldg(p + iy[j]);
            rx += v.x * wy[j];
            ry += v.y * wy[j];
        }
        sx += wx[i] * rx;
        sy += wx[i] * ry;
    }

    // warp = one coil, 32 consecutive samples -> coalesced float2 store
    float2* o = (float2*)out;
    o[(size_t)coil * MPTS + m] = make_float2(sx, sy);
}

// ---------------------------------------------------------------------------
extern "C" void kernel_launch(void* const* d_in, const int* in_sizes, int n_in,
                              void* d_out, int out_size) {
    const float* img_r = (const float*)d_in[0];
    const float* img_i = (const float*)d_in[1];
    const float* sm_r  = (const float*)d_in[2];
    const float* sm_i  = (const float*)d_in[3];
    const float* kt    = (const float*)d_in[4];
    float* out = (float*)d_out;

    apod_kernel<<<1, 320>>>();
    row_fft_kernel<<<dim3(320, NCOIL), 320>>>(img_r, img_i, sm_r, sm_i);
    col_fft_kernel<<<dim3(GQ / COLS_PER_BLK, NCOIL), 320>>>();
    interp_kernel<<<MPTS / SAMP_PER_BLK, 384>>>(kt, out);
}

// round 3
// speedup vs baseline: 1.3795x; 1.3007x over previous
#include <cuda_runtime.h>
#include <cstdint>

#define GQ     640
#define NIMG   320
#define NCOIL  12
#define MPTS   102400
#define PI_F   3.14159265358979f
#define BETA_F 13.855101f      // pi * sqrt((6*1.5/2)^2 - 0.8)
#define INV_G  0.0015625f      // 1/640

// Scratch (zero-initialized at module load; middle rows of g_gridA are never
// written by anyone, so they remain zero across graph replays).
__device__ float2 g_gridA[NCOIL * GQ * GQ];                 // [coil][row][col]
__device__ float2 g_gridC[GQ * GQ * NCOIL];                 // [row][col][coil]
__device__ float  g_scale[NIMG];

__constant__ float c5r[5] = {1.0f, 0.30901699f, -0.80901699f, -0.80901699f, 0.30901699f};
__constant__ float c5i[5] = {0.0f, -0.95105652f, -0.58778525f, 0.58778525f, 0.95105652f};

// ---------------------------------------------------------------------------
// Modified Bessel I0 (Abramowitz & Stegun, ~2e-7 rel error)
// ---------------------------------------------------------------------------
__device__ __forceinline__ float i0f_dev(float x) {
    if (x < 3.75f) {
        float t = x * (1.0f / 3.75f);
        t *= t;
        return 1.0f + t * (3.5156229f + t * (3.0899424f + t * (1.2067492f
             + t * (0.2659732f + t * (0.0360768f + t * 0.0045813f)))));
    } else {
        float t = 3.75f / x;
        float p = 0.39894228f + t * (0.01328592f + t * (0.00225319f + t * (-0.00157565f
                + t * (0.00916281f + t * (-0.02057706f + t * (0.02635537f
                + t * (-0.01647633f + t * 0.00392377f)))))));
        return expf(x) * rsqrtf(x) * p;
    }
}

// Kaiser-Bessel kernel, support |u| <= 3 (J=6)
__device__ __forceinline__ float kbf(float u) {
    float m = fabsf(u) * (1.0f / 3.0f);
    float a = 1.0f - m * m;
    a = a > 0.0f ? a : 0.0f;
    float v = i0f_dev(BETA_F * sqrtf(a)) * (1.0f / 6.0f);
    return (m <= 1.0f) ? v : 0.0f;
}

// ---------------------------------------------------------------------------
// Apodization scale (length 320, same for both dims: N=320, G=640)
// ---------------------------------------------------------------------------
__global__ void apod_kernel() {
    int n = threadIdx.x;
    if (n < NIMG) {
        float acc = 0.0f;
        #pragma unroll
        for (int j = -6; j <= 6; j++) {
            float kv = kbf((float)j);
            acc += kv * cosf(2.0f * PI_F * (float)j * ((float)n - 160.0f) * (1.0f / 640.0f));
        }
        g_scale[n] = 1.0f / acc;
    }
}

// ---------------------------------------------------------------------------
// 640-point forward FFT in shared memory. 640 = 5 * 128.
// Input layout in A:  A[n1*128 + n2] = x[5*n2 + n1]
// Output (natural order X[k]) ends in A. Requires blockDim.x == 320.
// ---------------------------------------------------------------------------
__device__ void fft640(float2* A, float2* B, int t) {
    float2* src = A;
    float2* dst = B;
    int n = 128;
    const int n1 = t >> 6;
    const int b  = t & 63;
    #pragma unroll
    for (int stage = 0; stage < 7; stage++) {
        int s = 1 << stage;
        int m = n >> 1;
        int q = b & (s - 1);
        int p = b >> stage;
        float2 a  = src[(n1 << 7) + q + s * p];
        float2 bb = src[(n1 << 7) + q + s * (p + m)];
        float ang = -(2.0f * PI_F) * (float)p / (float)n;
        float sn, cs;
        __sincosf(ang, &sn, &cs);
        float2 e = make_float2(a.x + bb.x, a.y + bb.y);
        float dx = a.x - bb.x, dy = a.y - bb.y;
        float2 o = make_float2(dx * cs - dy * sn, dx * sn + dy * cs);
        dst[(n1 << 7) + q + s * 2 * p]       = e;
        dst[(n1 << 7) + q + s * (2 * p + 1)] = o;
        __syncthreads();
        float2* tmp = src; src = dst; dst = tmp;
        n = m;
    }
    if (t < 128) {
        int k2 = t;
        float2 g[5];
        #pragma unroll
        for (int j = 0; j < 5; j++) {
            float2 f = src[(j << 7) + k2];
            int idx = (j * k2) % 640;
            if (idx >= 320) idx -= 640;
            float ang = -(2.0f * PI_F / 640.0f) * (float)idx;
            float sn, cs;
            __sincosf(ang, &sn, &cs);
            g[j] = make_float2(f.x * cs - f.y * sn, f.x * sn + f.y * cs);
        }
        #pragma unroll
        for (int k1 = 0; k1 < 5; k1++) {
            float rx = 0.0f, ry = 0.0f;
            #pragma unroll
            for (int j = 0; j < 5; j++) {
                int id = (j * k1) % 5;
                float cr = c5r[id], ci = c5i[id];
                rx += g[j].x * cr - g[j].y * ci;
                ry += g[j].x * ci + g[j].y * cr;
            }
            dst[(k1 << 7) + k2] = make_float2(rx, ry);
        }
    }
    __syncthreads();
}

// ---------------------------------------------------------------------------
// Row pass: fused coil-multiply + apodization + pad + ifftshift + row FFT.
// ---------------------------------------------------------------------------
__global__ void row_fft_kernel(const float* __restrict__ img_r, const float* __restrict__ img_i,
                               const float* __restrict__ sm_r,  const float* __restrict__ sm_i) {
    __shared__ float2 A[GQ];
    __shared__ float2 B[GQ];
    int coil = blockIdx.y;
    int rr   = blockIdx.x;
    int r = (rr < 160) ? rr : rr + 320;
    int i = (rr < 160) ? rr + 160 : rr - 160;
    int t = threadIdx.x;
    float si = g_scale[i];

    #pragma unroll
    for (int kk = 0; kk < 2; kk++) {
        int cc = t + kk * 320;
        float2 v = make_float2(0.0f, 0.0f);
        if (cc < 160 || cc >= 480) {
            int j = (cc < 160) ? cc + 160 : cc - 480;
            float ir  = img_r[i * NIMG + j];
            float ii  = img_i[i * NIMG + j];
            float sr  = sm_r[((size_t)coil * NIMG + i) * NIMG + j];
            float sim = sm_i[((size_t)coil * NIMG + i) * NIMG + j];
            float sc  = si * g_scale[j];
            v.x = (ir * sr - ii * sim) * sc;
            v.y = (ir * sim + ii * sr) * sc;
        }
        A[(cc % 5) * 128 + cc / 5] = v;
    }
    __syncthreads();
    fft640(A, B, t);
    float2* gout = g_gridA + ((size_t)coil * GQ + r) * GQ;
    for (int k = t; k < GQ; k += 320) gout[k] = A[k];
}

// ---------------------------------------------------------------------------
// Column pass: 4 columns per block staged through SMEM for coalesced loads.
// Writes coil-INTERLEAVED grid: g_gridC[(row*GQ+col)*NCOIL + coil] (x 1/640).
// ---------------------------------------------------------------------------
#define COLS_PER_BLK 4
#define SPITCH 642
__global__ void col_fft_kernel() {
    __shared__ float2 S[COLS_PER_BLK * SPITCH];
    __shared__ float2 A[GQ];
    __shared__ float2 B[GQ];
    int coil = blockIdx.y;
    int c0 = blockIdx.x * COLS_PER_BLK;
    const float2* gin = g_gridA + (size_t)coil * GQ * GQ;

    for (int idx = threadIdx.x; idx < GQ * COLS_PER_BLK; idx += 320) {
        int row = idx >> 2, col = idx & 3;
        S[col * SPITCH + row] = gin[(size_t)row * GQ + c0 + col];
    }
    __syncthreads();

    for (int col = 0; col < COLS_PER_BLK; col++) {
        for (int k = threadIdx.x; k < GQ; k += 320)
            A[(k % 5) * 128 + k / 5] = S[col * SPITCH + k];
        __syncthreads();
        fft640(A, B, threadIdx.x);
        // direct interleaved store (scattered, small cost)
        for (int k = threadIdx.x; k < GQ; k += 320) {
            float2 v = A[k];
            g_gridC[((size_t)k * GQ + c0 + col) * NCOIL + coil] =
                make_float2(v.x * INV_G, v.y * INV_G);
        }
        __syncthreads();
    }
}

// ---------------------------------------------------------------------------
// Interpolation v3: ONE WARP PER SAMPLE on the coil-interleaved grid.
// Each patch row = 6 cols x 12 coils = 72 consecutive float2 (576 B) ->
// 3 coalesced LDG.64 per row, 18 loads per sample for all 12 coils.
// Lanes 0..11 compute the 12 taps (6 x-taps, 6 y-taps); shfl-broadcast.
// Per-lane slot e = j*12+c accumulates sum_i wx[i]*v; wy applied at end;
// smem reduction 72 -> 12 coils; block-staged coalesced output store.
// ---------------------------------------------------------------------------
#define WPB 8   // warps (samples) per block
__global__ void __launch_bounds__(32 * WPB) interp_kernel(const float* __restrict__ ktraj,
                                                          float* __restrict__ out) {
    __shared__ float2 s_part[WPB][72];
    __shared__ float2 s_out[NCOIL][WPB];
    const int warp = threadIdx.x >> 5;
    const int lane = threadIdx.x & 31;
    const int m = blockIdx.x * WPB + warp;

    // --- taps in lanes 0..11: lane = dim*6 + j ---
    float w = 0.0f;
    int   ki = 0;
    if (lane < 12) {
        int dim = lane >= 6 ? 1 : 0;
        int j   = lane - dim * 6;
        float om = ktraj[dim * MPTS + m];
        float tt = fmodf((om * 640.0f) / 6.2831855f, 640.0f);
        if (tt < 0.0f) tt += 640.0f;
        float base = floorf(tt);
        float k = base + (float)(j - 2);
        w = kbf(tt - k);
        ki = (int)k;
        if (ki < 0) ki += 640;
        else if (ki >= 640) ki -= 640;
    }

    // --- slot assignment: e0 = lane, e1 = lane+32, e2 = lane+64 (lane<8) ---
    const int e0 = lane, e1 = lane + 32, e2 = lane + 64;
    const int j0 = e0 / 12, j1 = e1 / 12;            // j2 == 5
    const int cc0 = e0 - j0 * 12, cc1 = e1 - j1 * 12, cc2 = e2 - 60;

    const unsigned FULL = 0xFFFFFFFFu;
    float wy0 = __shfl_sync(FULL, w, 6 + j0);
    float wy1 = __shfl_sync(FULL, w, 6 + j1);
    float wy2 = __shfl_sync(FULL, w, 11);
    int   iy0 = __shfl_sync(FULL, ki, 6 + j0);
    int   iy1 = __shfl_sync(FULL, ki, 6 + j1);
    int   iy2 = __shfl_sync(FULL, ki, 11);
    const int off0 = iy0 * NCOIL + cc0;
    const int off1 = iy1 * NCOIL + cc1;
    const int off2 = iy2 * NCOIL + cc2;
    const bool has2 = (lane < 8);

    float2 acc0 = make_float2(0.f, 0.f);
    float2 acc1 = make_float2(0.f, 0.f);
    float2 acc2 = make_float2(0.f, 0.f);

    #pragma unroll
    for (int i = 0; i < 6; i++) {
        float wx = __shfl_sync(FULL, w, i);
        int   ix = __shfl_sync(FULL, ki, i);
        const float2* __restrict__ rowp = g_gridC + (size_t)ix * (GQ * NCOIL);
        float2 v0 = __ldg(rowp + off0);
        float2 v1 = __ldg(rowp + off1);
        acc0.x += wx * v0.x; acc0.y += wx * v0.y;
        acc1.x += wx * v1.x; acc1.y += wx * v1.y;
        if (has2) {
            float2 v2 = __ldg(rowp + off2);
            acc2.x += wx * v2.x; acc2.y += wx * v2.y;
        }
    }

    s_part[warp][e0] = make_float2(wy0 * acc0.x, wy0 * acc0.y);
    s_part[warp][e1] = make_float2(wy1 * acc1.x, wy1 * acc1.y);
    if (has2) s_part[warp][e2] = make_float2(wy2 * acc2.x, wy2 * acc2.y);
    __syncwarp();

    if (lane < 12) {
        float rx = 0.f, ry = 0.f;
        #pragma unroll
        for (int j = 0; j < 6; j++) {
            float2 p = s_part[warp][j * 12 + lane];
            rx += p.x; ry += p.y;
        }
        s_out[lane][warp] = make_float2(rx, ry);
    }
    __syncthreads();

    // coalesced-ish output: thread t<96 -> coil = t/8, sample slot = t%8
    if (threadIdx.x < NCOIL * WPB) {
        int c = threadIdx.x >> 3;
        int s = threadIdx.x & 7;
        ((float2*)out)[(size_t)c * MPTS + blockIdx.x * WPB + s] = s_out[c][s];
    }
}

// ---------------------------------------------------------------------------
extern "C" void kernel_launch(void* const* d_in, const int* in_sizes, int n_in,
                              void* d_out, int out_size) {
    const float* img_r = (const float*)d_in[0];
    const float* img_i = (const float*)d_in[1];
    const float* sm_r  = (const float*)d_in[2];
    const float* sm_i  = (const float*)d_in[3];
    const float* kt    = (const float*)d_in[4];
    float* out = (float*)d_out;

    apod_kernel<<<1, 320>>>();
    row_fft_kernel<<<dim3(320, NCOIL), 320>>>(img_r, img_i, sm_r, sm_i);
    col_fft_kernel<<<dim3(GQ / COLS_PER_BLK, NCOIL), 320>>>();
    interp_kernel<<<MPTS / WPB, 32 * WPB>>>(kt, out);
}